// round 2
// baseline (speedup 1.0000x reference)
#include <cuda_runtime.h>
#include <cuda.h>
#include <cuda_bf16.h>
#include <cstdint>

// ---------------- arch feature detection ----------------
// tcgen05 is only legal on sm_100a/101a/103a and family (f) targets.
// The harness may compile for plain sm_103 (no suffix) where tcgen05 is
// unavailable -> we provide an mma.sync fallback there.
#if defined(__CUDA_ARCH__)
#  if defined(__CUDA_ARCH_FEAT_SM103_ALL) || defined(__CUDA_ARCH_FEAT_SM100_ALL) || \
      (defined(__CUDA_ARCH_SPECIFIC__) && (__CUDA_ARCH_SPECIFIC__ >= 1000)) || \
      (defined(__CUDA_ARCH_FAMILY_SPECIFIC__) && (__CUDA_ARCH_FAMILY_SPECIFIC__ >= 1000))
#    define HAS_TCGEN05 1
#  else
#    define HAS_TCGEN05 0
#  endif
#else
#  define HAS_TCGEN05 0
#endif

// ---------------- problem dims ----------------
#define BB 16
#define CC 64
#define HH 112
#define WW 112
#define NN 256
#define HP 114
#define WP 144
#define C2 128

// ---------------- device scratch (no allocation allowed) ----------------
static __device__ __align__(1024) __nv_bfloat16 g_xp[(size_t)BB * HP * WP * C2]; // ~67 MB
static __device__ __align__(1024) __nv_bfloat16 g_wk[9 * NN * C2];               // ~590 KB
static __device__ float g_cn[NN];

// ---------------- PTX helpers ----------------
__device__ __forceinline__ uint32_t smem_to_u32(const void* smem_ptr) {
    uint32_t addr;
    asm("{ .reg .u64 tmp; cvta.to.shared.u64 tmp, %1; cvt.u32.u64 %0, tmp; }"
        : "=r"(addr) : "l"(smem_ptr));
    return addr;
}

#define MBARRIER_INIT(mbar_smem_addr, count) \
    asm volatile("mbarrier.init.shared.b64 [%0], %1;" \
        :: "r"((uint32_t)(mbar_smem_addr)), "r"((uint32_t)(count)) : "memory")
#define MBARRIER_EXPECT_TX(mbar_smem_addr, tx_bytes) \
    asm volatile("mbarrier.arrive.expect_tx.shared.b64 _, [%0], %1;" \
        :: "r"((uint32_t)(mbar_smem_addr)), "r"((uint32_t)(tx_bytes)) : "memory")

#define MBARRIER_WAIT_PARITY(mbar_smem_addr, phase_parity) do { \
    uint32_t _mbar = (uint32_t)(mbar_smem_addr); \
    uint32_t _parity = (uint32_t)(phase_parity); \
    uint32_t _done; \
    asm volatile( \
        "{\n\t.reg .pred p;\n\t" \
        "mbarrier.try_wait.parity.acquire.cta.shared::cta.b64 p, [%1], %2;\n\t" \
        "selp.b32 %0, 1, 0, p;\n\t}" \
        : "=r"(_done) : "r"(_mbar), "r"(_parity) : "memory"); \
    if (!_done) { \
        asm volatile( \
            "{\n\t.reg .pred P1;\n\t" \
            "WAIT_LOOP_%=:\n\t" \
            "mbarrier.try_wait.parity.acquire.cta.shared::cta.b64 P1, [%0], %1, 0x989680;\n\t" \
            "@P1 bra.uni WAIT_DONE_%=;\n\t" \
            "bra.uni WAIT_LOOP_%=;\n\t" \
            "WAIT_DONE_%=:\n\t}" \
            :: "r"(_mbar), "r"(_parity) : "memory"); \
    } \
} while (0)

#define TMA_LOAD_3D(smem_addr, tensor_map, coord_x, coord_y, coord_z, mbar_smem_addr) \
    asm volatile( \
        "cp.async.bulk.tensor.3d.shared::cta.global.tile.mbarrier::complete_tx::bytes " \
        "[%0], [%1, {%2, %3, %4}], [%5];" \
        :: "r"((uint32_t)(smem_addr)), "l"(tensor_map), \
           "r"((int32_t)(coord_x)), "r"((int32_t)(coord_y)), "r"((int32_t)(coord_z)), \
           "r"((uint32_t)(mbar_smem_addr)) : "memory")

#if HAS_TCGEN05
#define TCGEN05_ALLOC(smem_result_addr, nCols) \
    asm volatile("tcgen05.alloc.cta_group::1.sync.aligned.shared::cta.b32 [%0], %1;" \
        :: "r"((uint32_t)(smem_result_addr)), "r"((uint32_t)(nCols)) : "memory")
#define TCGEN05_DEALLOC(tmem_addr, nCols) \
    asm volatile("tcgen05.dealloc.cta_group::1.sync.aligned.b32 %0, %1;" \
        :: "r"(tmem_addr), "r"((uint32_t)(nCols)))
#define TCGEN05_RELINQUISH_ALLOC_PERMIT() \
    asm volatile("tcgen05.relinquish_alloc_permit.cta_group::1.sync.aligned;")
#define TCGEN05_COMMIT(mbar_smem_addr) \
    asm volatile("tcgen05.commit.cta_group::1.mbarrier::arrive::one.shared::cluster.b64 [%0];" \
        :: "r"((uint32_t)(mbar_smem_addr)) : "memory")
#define TCGEN05_FENCE_AFTER() \
    asm volatile("tcgen05.fence::after_thread_sync;" ::: "memory")
#define TCGEN05_FENCE_BEFORE() \
    asm volatile("tcgen05.fence::before_thread_sync;" ::: "memory")
#define TCGEN05_WAIT_LD() \
    asm volatile("tcgen05.wait::ld.sync.aligned;" ::: "memory")

#define TCGEN05_LD_32X32B_X32(r, tmem_addr) \
    asm volatile( \
        "tcgen05.ld.sync.aligned.32x32b.x32.b32 " \
        "{%0, %1, %2, %3, %4, %5, %6, %7, " \
        " %8, %9, %10, %11, %12, %13, %14, %15, " \
        " %16, %17, %18, %19, %20, %21, %22, %23, " \
        " %24, %25, %26, %27, %28, %29, %30, %31}, [%32];" \
        : "=r"((r)[0]),  "=r"((r)[1]),  "=r"((r)[2]),  "=r"((r)[3]), \
          "=r"((r)[4]),  "=r"((r)[5]),  "=r"((r)[6]),  "=r"((r)[7]), \
          "=r"((r)[8]),  "=r"((r)[9]),  "=r"((r)[10]), "=r"((r)[11]), \
          "=r"((r)[12]), "=r"((r)[13]), "=r"((r)[14]), "=r"((r)[15]), \
          "=r"((r)[16]), "=r"((r)[17]), "=r"((r)[18]), "=r"((r)[19]), \
          "=r"((r)[20]), "=r"((r)[21]), "=r"((r)[22]), "=r"((r)[23]), \
          "=r"((r)[24]), "=r"((r)[25]), "=r"((r)[26]), "=r"((r)[27]), \
          "=r"((r)[28]), "=r"((r)[29]), "=r"((r)[30]), "=r"((r)[31]) \
        : "r"(tmem_addr))

// SW128 K-major descriptor: layout=2, version=1, SBO=64, LBO=1
static constexpr uint64_t SMEM_DESC_BASE_SW128 =
    (uint64_t(2) << 61) | (uint64_t(1) << 46) | (uint64_t(64) << 32) | (uint64_t(1) << 16);
#define MAKE_SMEM_DESC(base_addr) \
    (SMEM_DESC_BASE_SW128 | ((uint64_t)((base_addr) >> 4) & 0x3FFF))

__device__ __forceinline__ void mma_f16_ss(uint32_t d_tmem, uint64_t a_desc, uint64_t b_desc,
                                           uint32_t idesc, bool acc) {
    uint32_t en = acc ? 1u : 0u;
    asm volatile(
        "{\n\t.reg .pred p;\n\t"
        "setp.ne.u32 p, %5, 0;\n\t"
        "tcgen05.mma.cta_group::1.kind::f16 [%0], %1, %2, %3, {%4, %4, %4, %4}, p;\n\t}"
        :: "r"(d_tmem), "l"(a_desc), "l"(b_desc), "r"(idesc), "r"(0u), "r"(en)
        : "memory");
}
#endif  // HAS_TCGEN05

// fallback primitives (legal on plain sm_103 / sm_80+)
__device__ __forceinline__ void ldsm4(uint32_t* r, uint32_t addr) {
    asm volatile("ldmatrix.sync.aligned.m8n8.x4.shared.b16 {%0,%1,%2,%3}, [%4];"
        : "=r"(r[0]), "=r"(r[1]), "=r"(r[2]), "=r"(r[3]) : "r"(addr));
}
__device__ __forceinline__ void mma16816(float* d, const uint32_t* a, uint32_t b0, uint32_t b1) {
    asm volatile(
        "mma.sync.aligned.m16n8k16.row.col.f32.bf16.bf16.f32 "
        "{%0,%1,%2,%3}, {%4,%5,%6,%7}, {%8,%9}, {%0,%1,%2,%3};"
        : "+f"(d[0]), "+f"(d[1]), "+f"(d[2]), "+f"(d[3])
        : "r"(a[0]), "r"(a[1]), "r"(a[2]), "r"(a[3]), "r"(b0), "r"(b1));
}

// ---------------- preprocessing kernels ----------------
__global__ void sim_zero_xp() {
    size_t n16 = ((size_t)BB * HP * WP * C2) / 8;
    uint4* p = reinterpret_cast<uint4*>(g_xp);
    uint4 z; z.x = z.y = z.z = z.w = 0u;
    for (size_t i = (size_t)blockIdx.x * blockDim.x + threadIdx.x; i < n16;
         i += (size_t)gridDim.x * blockDim.x)
        p[i] = z;
}

__global__ void sim_fill_xp(const float* __restrict__ x) {
    __shared__ float tile[64][33];
    int w0 = blockIdx.x * 32;
    int h = blockIdx.y, b = blockIdx.z;
    int lane = threadIdx.x & 31, warp = threadIdx.x >> 5;
    int w = w0 + lane;
#pragma unroll
    for (int k = 0; k < 8; k++) {
        int c = warp * 8 + k;
        float v = 0.f;
        if (w < WW) v = x[(((size_t)b * CC + c) * HH + h) * WW + w];
        tile[c][lane] = v;
    }
    __syncthreads();
    int p = threadIdx.x >> 3, cg = threadIdx.x & 7;
    int wo = w0 + p;
    if (wo < WW) {
        __nv_bfloat16* dst = g_xp + (((size_t)b * HP + (h + 1)) * WP + (wo + 1)) * C2;
        __nv_bfloat162 sq[4], xv[4];
#pragma unroll
        for (int t = 0; t < 4; t++) {
            float v0 = tile[cg * 8 + 2 * t][p];
            float v1 = tile[cg * 8 + 2 * t + 1][p];
            sq[t] = __floats2bfloat162_rn(v0 * v0, v1 * v1);
            xv[t] = __floats2bfloat162_rn(v0, v1);
        }
        *reinterpret_cast<uint4*>(dst + cg * 8) = *reinterpret_cast<const uint4*>(sq);
        *reinterpret_cast<uint4*>(dst + 64 + cg * 8) = *reinterpret_cast<const uint4*>(xv);
    }
}

__global__ void sim_prep_w(const float* __restrict__ sw, const float* __restrict__ tm) {
    int n = blockIdx.x, c = threadIdx.x;
    float csum = 0.f;
#pragma unroll
    for (int p = 0; p < 3; p++)
#pragma unroll
        for (int q = 0; q < 3; q++) {
            size_t idx = (((size_t)n * CC + c) * 3 + p) * 3 + q;
            float w = fabsf(sw[idx]);
            float t = tm[idx];
            csum += w * t * t;
            size_t o = ((size_t)(p * 3 + q) * NN + n) * C2;
            g_wk[o + c] = __float2bfloat16(-w);
            g_wk[o + 64 + c] = __float2bfloat16(2.f * w * t);
        }
    __shared__ float red[64];
    red[c] = csum;
    __syncthreads();
    for (int s = 32; s > 0; s >>= 1) {
        if (c < s) red[c] += red[c + s];
        __syncthreads();
    }
    if (c == 0) g_cn[n] = red[0];
}

// ---------------- main conv kernel ----------------
#define SM_TMEM      0
#define SM_BAR_FULL  16
#define SM_BAR_EMPTY 32
#define SM_BAR_DONE  48
#define SM_CN        1024
#define SM_STAGE     2048
#define A_BYTES      32768
#define B_BYTES      65536
#define STAGE_BYTES  (A_BYTES + B_BYTES)
#define CONV_SMEM    (SM_STAGE + 2 * STAGE_BYTES)

#if HAS_TCGEN05
static constexpr uint32_t CONV_IDESC =
    (1u << 4) | (1u << 7) | (1u << 10) | ((NN / 8) << 17) | ((128 / 16) << 24);
#endif

__device__ __forceinline__ void conv_issue_tma(
    const CUtensorMap* tmx, const CUtensorMap* tmw,
    uint32_t sb, int stage, int step, int b, int i)
{
    int p = step / 3, q = step % 3;
    uint32_t abase = sb + SM_STAGE + stage * STAGE_BYTES;
    uint32_t bbase = abase + A_BYTES;
    uint32_t bar = sb + SM_BAR_FULL + stage * 8;
    MBARRIER_EXPECT_TX(bar, STAGE_BYTES);
    int z = b * HP + i + p;
    TMA_LOAD_3D(abase,         tmx, 0,  q, z, bar);
    TMA_LOAD_3D(abase + 16384, tmx, 64, q, z, bar);
    TMA_LOAD_3D(bbase,         tmw, 0,  0, step, bar);
    TMA_LOAD_3D(bbase + 32768, tmw, 64, 0, step, bar);
}

__global__ void __launch_bounds__(256, 1) sim_conv(
    const __grid_constant__ CUtensorMap tmx,
    const __grid_constant__ CUtensorMap tmw,
    float* __restrict__ out)
{
    extern __shared__ char smem[];
    uint32_t sb = smem_to_u32(smem);
    int tid = threadIdx.x, wid = tid >> 5, lane = tid & 31;
    int bx = blockIdx.x;
    int b = bx / HH, i = bx % HH;

    for (int k = tid; k < NN; k += 256)
        reinterpret_cast<float*>(smem + SM_CN)[k] = g_cn[k];
    if (tid == 0) {
        MBARRIER_INIT(sb + SM_BAR_FULL + 0, 1);
        MBARRIER_INIT(sb + SM_BAR_FULL + 8, 1);
        MBARRIER_INIT(sb + SM_BAR_EMPTY + 0, 1);
        MBARRIER_INIT(sb + SM_BAR_EMPTY + 8, 1);
        MBARRIER_INIT(sb + SM_BAR_DONE, 1);
    }

#if HAS_TCGEN05
    // ================= tcgen05 path =================
    if (wid == 0) {
        TCGEN05_ALLOC(sb + SM_TMEM, 256);
        TCGEN05_RELINQUISH_ALLOC_PERMIT();
    }
    __syncthreads();

    uint32_t tmem;
    asm volatile("ld.shared.b32 %0, [%1];" : "=r"(tmem) : "r"(sb + SM_TMEM));

    if (tid == 0) {
        conv_issue_tma(&tmx, &tmw, sb, 0, 0, b, i);
        conv_issue_tma(&tmx, &tmw, sb, 1, 1, b, i);
        for (int step = 0; step < 9; step++) {
            int st = step & 1;
            int ph = (step >> 1) & 1;
            MBARRIER_WAIT_PARITY(sb + SM_BAR_FULL + st * 8, ph);
            uint32_t abase = sb + SM_STAGE + st * STAGE_BYTES;
            uint64_t ad = MAKE_SMEM_DESC(abase);
            uint64_t bd = MAKE_SMEM_DESC(abase + A_BYTES);
#pragma unroll
            for (int k = 0; k < 8; k++) {
                uint32_t ao = (k < 4) ? 2 * k : 1024 + 2 * (k - 4);
                uint32_t bo = (k < 4) ? 2 * k : 2048 + 2 * (k - 4);
                mma_f16_ss(tmem, ad + ao, bd + bo, CONV_IDESC, (step + k) != 0);
            }
            if (step < 7) {
                TCGEN05_COMMIT(sb + SM_BAR_EMPTY + st * 8);
                MBARRIER_WAIT_PARITY(sb + SM_BAR_EMPTY + st * 8, ph);
                conv_issue_tma(&tmx, &tmw, sb, st, step + 2, b, i);
            } else if (step == 8) {
                TCGEN05_COMMIT(sb + SM_BAR_DONE);
            }
        }
    }

    MBARRIER_WAIT_PARITY(sb + SM_BAR_DONE, 0);
    TCGEN05_FENCE_AFTER();

    // 8 warps: warps 0-3 cols 0..127, warps 4-7 cols 128..255; rows (wid&3)*32
    int j = (wid & 3) * 32 + lane;
    int cbase = (wid >> 2) * 128;
    const float* cn = reinterpret_cast<const float*>(smem + SM_CN);
    for (int cc = 0; cc < 128; cc += 32) {
        int c0 = cbase + cc;
        uint32_t r[32];
        TCGEN05_LD_32X32B_X32(r, tmem + c0);
        TCGEN05_WAIT_LD();
        if (j < WW) {
            float* po = out + (((size_t)(b * NN + c0)) * HH + i) * WW + j;
#pragma unroll
            for (int c = 0; c < 32; c++)
                po[(size_t)c * (HH * WW)] = __uint_as_float(r[c]) - cn[c0 + c];
        }
    }
    TCGEN05_FENCE_BEFORE();
    __syncthreads();
    if (wid == 0) TCGEN05_DEALLOC(tmem, 256);

#else
    // ================= mma.sync fallback (plain sm_103) =================
    __syncthreads();

    int mw = wid & 3;          // row block: 32*mw
    int nw = wid >> 2;         // col block: 128*nw
    float acc[2][16][4];
#pragma unroll
    for (int a = 0; a < 2; a++)
#pragma unroll
        for (int t = 0; t < 16; t++)
#pragma unroll
            for (int r = 0; r < 4; r++) acc[a][t][r] = 0.f;

    // per-thread ldmatrix addressing components
    int mat = lane >> 3;                 // 0..3
    int mrow = lane & 7;
    int rsel = (mat & 1) << 3;           // +8 rows for mats 1,3
    int csel = (mat >> 1) << 4;          // +16B for mats 2,3

    if (tid == 0) {
        conv_issue_tma(&tmx, &tmw, sb, 0, 0, b, i);
        conv_issue_tma(&tmx, &tmw, sb, 1, 1, b, i);
    }

    for (int step = 0; step < 9; step++) {
        int st = step & 1;
        int ph = (step >> 1) & 1;
        MBARRIER_WAIT_PARITY(sb + SM_BAR_FULL + st * 8, ph);
        uint32_t abase = sb + SM_STAGE + st * STAGE_BYTES;
        uint32_t bbase = abase + A_BYTES;

#pragma unroll
        for (int blk = 0; blk < 2; blk++) {
#pragma unroll
            for (int kk = 0; kk < 4; kk++) {
                int cb = kk * 32 + csel;
                // A frags: 2 m16 tiles
                uint32_t afr[2][4];
#pragma unroll
                for (int mt = 0; mt < 2; mt++) {
                    int row = mw * 32 + mt * 16 + mrow + rsel;
                    uint32_t ad = abase + blk * 16384 + row * 128 + (cb ^ ((row & 7) << 4));
                    ldsm4(afr[mt], ad);
                }
                // B frags: 16 n-tiles, 2 per ldmatrix.x4
#pragma unroll
                for (int g = 0; g < 8; g++) {
                    int row = nw * 128 + g * 16 + mrow + rsel;
                    uint32_t bd = bbase + blk * 32768 + row * 128 + (cb ^ ((row & 7) << 4));
                    uint32_t bf[4];
                    ldsm4(bf, bd);
                    mma16816(acc[0][2 * g],     afr[0], bf[0], bf[2]);
                    mma16816(acc[0][2 * g + 1], afr[0], bf[1], bf[3]);
                    mma16816(acc[1][2 * g],     afr[1], bf[0], bf[2]);
                    mma16816(acc[1][2 * g + 1], afr[1], bf[1], bf[3]);
                }
            }
        }
        __syncthreads();
        if (tid == 0 && step < 7) conv_issue_tma(&tmx, &tmw, sb, st, step + 2, b, i);
    }

    // epilogue: transpose through SMEM for coalesced stores
    float* ep = reinterpret_cast<float*>(smem + SM_STAGE);
#pragma unroll
    for (int mt = 0; mt < 2; mt++)
#pragma unroll
        for (int nt = 0; nt < 16; nt++)
#pragma unroll
            for (int r = 0; r < 4; r++) {
                int n = nw * 128 + nt * 8 + 2 * (lane & 3) + (r & 1);
                int j = mw * 32 + mt * 16 + (lane >> 2) + ((r >> 1) << 3);
                ep[n * 132 + j] = acc[mt][nt][r];
            }
    __syncthreads();

    const float* cn = reinterpret_cast<const float*>(smem + SM_CN);
    int jj = tid & 127;
    int half = tid >> 7;
    if (jj < WW) {
        for (int n0 = 0; n0 < NN; n0 += 2) {
            int n = n0 + half;
            out[(((size_t)b * NN + n) * HH + i) * WW + jj] = ep[n * 132 + jj] - cn[n];
        }
    }
#endif
}

// ---------------- host launcher ----------------
typedef CUresult (*PFN_encodeTiled)(
    CUtensorMap*, CUtensorMapDataType, cuuint32_t, void*,
    const cuuint64_t*, const cuuint64_t*, const cuuint32_t*, const cuuint32_t*,
    CUtensorMapInterleave, CUtensorMapSwizzle, CUtensorMapL2promotion,
    CUtensorMapFloatOOBfill);

extern "C" void kernel_launch(void* const* d_in, const int* in_sizes, int n_in,
                              void* d_out, int out_size) {
    const float* x  = (const float*)d_in[0];
    const float* sw = (const float*)d_in[1];
    const float* tm = (const float*)d_in[2];
    float* out = (float*)d_out;

    static PFN_encodeTiled enc = nullptr;
    if (!enc) {
        void* fp = nullptr;
        cudaDriverEntryPointQueryResult qr;
        cudaGetDriverEntryPoint("cuTensorMapEncodeTiled", &fp, cudaEnableDefault, &qr);
        enc = (PFN_encodeTiled)fp;
    }
    if (!enc) return;

    void* xp_ptr = nullptr;
    void* wk_ptr = nullptr;
    cudaGetSymbolAddress(&xp_ptr, g_xp);
    cudaGetSymbolAddress(&wk_ptr, g_wk);

    CUtensorMap tmx, tmw;
    {
        cuuint64_t dims[3]    = {C2, WP, (cuuint64_t)BB * HP};
        cuuint64_t strides[2] = {(cuuint64_t)C2 * 2, (cuuint64_t)WP * C2 * 2};
        cuuint32_t box[3]     = {64, 128, 1};
        cuuint32_t es[3]      = {1, 1, 1};
        enc(&tmx, CU_TENSOR_MAP_DATA_TYPE_BFLOAT16, 3, xp_ptr, dims, strides, box, es,
            CU_TENSOR_MAP_INTERLEAVE_NONE, CU_TENSOR_MAP_SWIZZLE_128B,
            CU_TENSOR_MAP_L2_PROMOTION_L2_128B, CU_TENSOR_MAP_FLOAT_OOB_FILL_NONE);
    }
    {
        cuuint64_t dims[3]    = {C2, NN, 9};
        cuuint64_t strides[2] = {(cuuint64_t)C2 * 2, (cuuint64_t)NN * C2 * 2};
        cuuint32_t box[3]     = {64, 256, 1};
        cuuint32_t es[3]      = {1, 1, 1};
        enc(&tmw, CU_TENSOR_MAP_DATA_TYPE_BFLOAT16, 3, wk_ptr, dims, strides, box, es,
            CU_TENSOR_MAP_INTERLEAVE_NONE, CU_TENSOR_MAP_SWIZZLE_128B,
            CU_TENSOR_MAP_L2_PROMOTION_L2_128B, CU_TENSOR_MAP_FLOAT_OOB_FILL_NONE);
    }

    cudaFuncSetAttribute(sim_conv, cudaFuncAttributeMaxDynamicSharedMemorySize, CONV_SMEM);

    sim_zero_xp<<<2048, 256>>>();
    sim_fill_xp<<<dim3(4, HH, BB), 256>>>(x);
    sim_prep_w<<<NN, 64>>>(sw, tm);
    sim_conv<<<BB * HH, 256, CONV_SMEM>>>(tmx, tmw, out);
}

// round 3
// speedup vs baseline: 1.0658x; 1.0658x over previous
#include <cuda_runtime.h>
#include <cuda.h>
#include <cuda_bf16.h>
#include <cstdint>

// ---------------- arch feature detection ----------------
#if defined(__CUDA_ARCH__)
#  if defined(__CUDA_ARCH_FEAT_SM103_ALL) || defined(__CUDA_ARCH_FEAT_SM100_ALL) || \
      (defined(__CUDA_ARCH_SPECIFIC__) && (__CUDA_ARCH_SPECIFIC__ >= 1000)) || \
      (defined(__CUDA_ARCH_FAMILY_SPECIFIC__) && (__CUDA_ARCH_FAMILY_SPECIFIC__ >= 1000))
#    define HAS_TCGEN05 1
#  else
#    define HAS_TCGEN05 0
#  endif
#else
#  define HAS_TCGEN05 0
#endif

// ---------------- problem dims ----------------
#define BB 16
#define CC 64
#define HH 112
#define WW 112
#define NN 256
#define HP 114
#define WP 144
#define C2 128

// ---------------- device scratch ----------------
static __device__ __align__(1024) __nv_bfloat16 g_xp[(size_t)BB * HP * WP * C2]; // ~67 MB
static __device__ __align__(1024) __nv_bfloat16 g_wk[9 * NN * C2];               // ~590 KB
static __device__ float g_cn[NN];

// ---------------- PTX helpers ----------------
__device__ __forceinline__ uint32_t smem_to_u32(const void* smem_ptr) {
    uint32_t addr;
    asm("{ .reg .u64 tmp; cvta.to.shared.u64 tmp, %1; cvt.u32.u64 %0, tmp; }"
        : "=r"(addr) : "l"(smem_ptr));
    return addr;
}

#define MBARRIER_INIT(mbar_smem_addr, count) \
    asm volatile("mbarrier.init.shared.b64 [%0], %1;" \
        :: "r"((uint32_t)(mbar_smem_addr)), "r"((uint32_t)(count)) : "memory")
#define MBARRIER_EXPECT_TX(mbar_smem_addr, tx_bytes) \
    asm volatile("mbarrier.arrive.expect_tx.shared.b64 _, [%0], %1;" \
        :: "r"((uint32_t)(mbar_smem_addr)), "r"((uint32_t)(tx_bytes)) : "memory")

#define MBARRIER_WAIT_PARITY(mbar_smem_addr, phase_parity) do { \
    uint32_t _mbar = (uint32_t)(mbar_smem_addr); \
    uint32_t _parity = (uint32_t)(phase_parity); \
    uint32_t _done; \
    asm volatile( \
        "{\n\t.reg .pred p;\n\t" \
        "mbarrier.try_wait.parity.acquire.cta.shared::cta.b64 p, [%1], %2;\n\t" \
        "selp.b32 %0, 1, 0, p;\n\t}" \
        : "=r"(_done) : "r"(_mbar), "r"(_parity) : "memory"); \
    if (!_done) { \
        asm volatile( \
            "{\n\t.reg .pred P1;\n\t" \
            "WAIT_LOOP_%=:\n\t" \
            "mbarrier.try_wait.parity.acquire.cta.shared::cta.b64 P1, [%0], %1, 0x989680;\n\t" \
            "@P1 bra.uni WAIT_DONE_%=;\n\t" \
            "bra.uni WAIT_LOOP_%=;\n\t" \
            "WAIT_DONE_%=:\n\t}" \
            :: "r"(_mbar), "r"(_parity) : "memory"); \
    } \
} while (0)

#define TMA_LOAD_3D(smem_addr, tensor_map, coord_x, coord_y, coord_z, mbar_smem_addr) \
    asm volatile( \
        "cp.async.bulk.tensor.3d.shared::cta.global.tile.mbarrier::complete_tx::bytes " \
        "[%0], [%1, {%2, %3, %4}], [%5];" \
        :: "r"((uint32_t)(smem_addr)), "l"(tensor_map), \
           "r"((int32_t)(coord_x)), "r"((int32_t)(coord_y)), "r"((int32_t)(coord_z)), \
           "r"((uint32_t)(mbar_smem_addr)) : "memory")

#if HAS_TCGEN05
#define TCGEN05_ALLOC(smem_result_addr, nCols) \
    asm volatile("tcgen05.alloc.cta_group::1.sync.aligned.shared::cta.b32 [%0], %1;" \
        :: "r"((uint32_t)(smem_result_addr)), "r"((uint32_t)(nCols)) : "memory")
#define TCGEN05_DEALLOC(tmem_addr, nCols) \
    asm volatile("tcgen05.dealloc.cta_group::1.sync.aligned.b32 %0, %1;" \
        :: "r"(tmem_addr), "r"((uint32_t)(nCols)))
#define TCGEN05_RELINQUISH_ALLOC_PERMIT() \
    asm volatile("tcgen05.relinquish_alloc_permit.cta_group::1.sync.aligned;")
#define TCGEN05_COMMIT(mbar_smem_addr) \
    asm volatile("tcgen05.commit.cta_group::1.mbarrier::arrive::one.shared::cluster.b64 [%0];" \
        :: "r"((uint32_t)(mbar_smem_addr)) : "memory")
#define TCGEN05_FENCE_AFTER() \
    asm volatile("tcgen05.fence::after_thread_sync;" ::: "memory")
#define TCGEN05_FENCE_BEFORE() \
    asm volatile("tcgen05.fence::before_thread_sync;" ::: "memory")
#define TCGEN05_WAIT_LD() \
    asm volatile("tcgen05.wait::ld.sync.aligned;" ::: "memory")

#define TCGEN05_LD_32X32B_X32(r, tmem_addr) \
    asm volatile( \
        "tcgen05.ld.sync.aligned.32x32b.x32.b32 " \
        "{%0, %1, %2, %3, %4, %5, %6, %7, " \
        " %8, %9, %10, %11, %12, %13, %14, %15, " \
        " %16, %17, %18, %19, %20, %21, %22, %23, " \
        " %24, %25, %26, %27, %28, %29, %30, %31}, [%32];" \
        : "=r"((r)[0]),  "=r"((r)[1]),  "=r"((r)[2]),  "=r"((r)[3]), \
          "=r"((r)[4]),  "=r"((r)[5]),  "=r"((r)[6]),  "=r"((r)[7]), \
          "=r"((r)[8]),  "=r"((r)[9]),  "=r"((r)[10]), "=r"((r)[11]), \
          "=r"((r)[12]), "=r"((r)[13]), "=r"((r)[14]), "=r"((r)[15]), \
          "=r"((r)[16]), "=r"((r)[17]), "=r"((r)[18]), "=r"((r)[19]), \
          "=r"((r)[20]), "=r"((r)[21]), "=r"((r)[22]), "=r"((r)[23]), \
          "=r"((r)[24]), "=r"((r)[25]), "=r"((r)[26]), "=r"((r)[27]), \
          "=r"((r)[28]), "=r"((r)[29]), "=r"((r)[30]), "=r"((r)[31]) \
        : "r"(tmem_addr))

static constexpr uint64_t SMEM_DESC_BASE_SW128 =
    (uint64_t(2) << 61) | (uint64_t(1) << 46) | (uint64_t(64) << 32) | (uint64_t(1) << 16);
#define MAKE_SMEM_DESC(base_addr) \
    (SMEM_DESC_BASE_SW128 | ((uint64_t)((base_addr) >> 4) & 0x3FFF))

__device__ __forceinline__ void mma_f16_ss(uint32_t d_tmem, uint64_t a_desc, uint64_t b_desc,
                                           uint32_t idesc, bool acc) {
    uint32_t en = acc ? 1u : 0u;
    asm volatile(
        "{\n\t.reg .pred p;\n\t"
        "setp.ne.u32 p, %5, 0;\n\t"
        "tcgen05.mma.cta_group::1.kind::f16 [%0], %1, %2, %3, {%4, %4, %4, %4}, p;\n\t}"
        :: "r"(d_tmem), "l"(a_desc), "l"(b_desc), "r"(idesc), "r"(0u), "r"(en)
        : "memory");
}
#endif  // HAS_TCGEN05

// ---------------- preprocessing kernels ----------------
// Builds padded NHWC bf16 tensor (x^2 | x), INCLUDING writing zeros to the halo
// (padded row 0/113, padded col 0 and 113..143). No separate zero pass needed.
__global__ void sim_fill_xp(const float* __restrict__ x) {
    __shared__ float tile[64][33];
    int pw0 = blockIdx.x * 32;     // padded col base (0,32,64,96,128)
    int py = blockIdx.y;           // padded row 0..113
    int b = blockIdx.z;
    int lane = threadIdx.x & 31, warp = threadIdx.x >> 5;
    int h = py - 1;
    bool rowvalid = (py >= 1 && py <= WW);  // interior rows 1..112
    int w = pw0 + lane - 1;                 // source col for padded col pw0+lane
#pragma unroll
    for (int k = 0; k < 8; k++) {
        int c = warp * 8 + k;
        float v = 0.f;
        if (rowvalid && w >= 0 && w < WW)
            v = x[(((size_t)b * CC + c) * HH + h) * WW + w];
        tile[c][lane] = v;
    }
    __syncthreads();
    int p = threadIdx.x >> 3, cg = threadIdx.x & 7;
    int pw = pw0 + p;
    if (pw < WP) {
        __nv_bfloat16* dst = g_xp + (((size_t)b * HP + py) * WP + pw) * C2;
        __nv_bfloat162 sq[4], xv[4];
#pragma unroll
        for (int t = 0; t < 4; t++) {
            float v0 = tile[cg * 8 + 2 * t][p];
            float v1 = tile[cg * 8 + 2 * t + 1][p];
            sq[t] = __floats2bfloat162_rn(v0 * v0, v1 * v1);
            xv[t] = __floats2bfloat162_rn(v0, v1);
        }
        *reinterpret_cast<uint4*>(dst + cg * 8) = *reinterpret_cast<const uint4*>(sq);
        *reinterpret_cast<uint4*>(dst + 64 + cg * 8) = *reinterpret_cast<const uint4*>(xv);
    }
}

__global__ void sim_prep_w(const float* __restrict__ sw, const float* __restrict__ tm) {
    int n = blockIdx.x, c = threadIdx.x;
    float csum = 0.f;
#pragma unroll
    for (int p = 0; p < 3; p++)
#pragma unroll
        for (int q = 0; q < 3; q++) {
            size_t idx = (((size_t)n * CC + c) * 3 + p) * 3 + q;
            float w = fabsf(sw[idx]);
            float t = tm[idx];
            csum += w * t * t;
            size_t o = ((size_t)(p * 3 + q) * NN + n) * C2;
            g_wk[o + c] = __float2bfloat16(-w);
            g_wk[o + 64 + c] = __float2bfloat16(2.f * w * t);
        }
    __shared__ float red[64];
    red[c] = csum;
    __syncthreads();
    for (int s = 32; s > 0; s >>= 1) {
        if (c < s) red[c] += red[c + s];
        __syncthreads();
    }
    if (c == 0) g_cn[n] = red[0];
}

// ---------------- main conv kernel ----------------
// R=2 output rows per CTA. Sub-stage = one K-half of one (p,q) step:
//   [ B half : 32KB ][ A row0 half : 16KB ][ A row1 half : 16KB ] = 64KB
// 3-deep pipeline, 18 sub-steps. TMEM: D0 at cols 0..255, D1 at 256..511.
#define SM_TMEM      0
#define SM_BAR_FULL  16    // 16,24,32
#define SM_BAR_EMPTY 48    // 48,56,64
#define SM_BAR_DONE  80
#define SM_CN        1024
#define SM_STAGE     2048
#define STAGE_BYTES  65536
#define OFF_A0       32768
#define OFF_A1       49152
#define NSTAGE       3
#define CONV_SMEM    (SM_STAGE + NSTAGE * STAGE_BYTES)   // 198656

#if HAS_TCGEN05
static constexpr uint32_t CONV_IDESC =
    (1u << 4) | (1u << 7) | (1u << 10) | ((NN / 8) << 17) | ((128 / 16) << 24);

__device__ __forceinline__ void conv_issue_tma(
    const CUtensorMap* tmx, const CUtensorMap* tmw,
    uint32_t sb, int s, int b, int i0)
{
    int step = s >> 1, kh = s & 1;
    int p = step / 3, q = step % 3;
    int st = s % NSTAGE;
    uint32_t sbase = sb + SM_STAGE + st * STAGE_BYTES;
    uint32_t bar = sb + SM_BAR_FULL + st * 8;
    MBARRIER_EXPECT_TX(bar, STAGE_BYTES);
    int z = b * HP + i0 + p;
    TMA_LOAD_3D(sbase,           tmw, 64 * kh, 0, step, bar);   // B half [256n x 64c]
    TMA_LOAD_3D(sbase + OFF_A0,  tmx, 64 * kh, q, z,     bar);  // A row0 half
    TMA_LOAD_3D(sbase + OFF_A1,  tmx, 64 * kh, q, z + 1, bar);  // A row1 half
}
#endif

__global__ void __launch_bounds__(256, 1) sim_conv(
    const __grid_constant__ CUtensorMap tmx,
    const __grid_constant__ CUtensorMap tmw,
    float* __restrict__ out)
{
    extern __shared__ char smem[];
    uint32_t sb = smem_to_u32(smem);
    int tid = threadIdx.x, wid = tid >> 5, lane = tid & 31;
    int bx = blockIdx.x;
    int b = bx / (HH / 2), i0 = (bx % (HH / 2)) * 2;

    for (int k = tid; k < NN; k += 256)
        reinterpret_cast<float*>(smem + SM_CN)[k] = g_cn[k];
    if (tid == 0) {
#pragma unroll
        for (int s = 0; s < NSTAGE; s++) {
            MBARRIER_INIT(sb + SM_BAR_FULL + s * 8, 1);
            MBARRIER_INIT(sb + SM_BAR_EMPTY + s * 8, 1);
        }
        MBARRIER_INIT(sb + SM_BAR_DONE, 1);
    }

#if HAS_TCGEN05
    if (wid == 0) {
        TCGEN05_ALLOC(sb + SM_TMEM, 512);
        TCGEN05_RELINQUISH_ALLOC_PERMIT();
    }
    __syncthreads();

    uint32_t tmem;
    asm volatile("ld.shared.b32 %0, [%1];" : "=r"(tmem) : "r"(sb + SM_TMEM));

    if (tid == 0) {
        conv_issue_tma(&tmx, &tmw, sb, 0, b, i0);
        conv_issue_tma(&tmx, &tmw, sb, 1, b, i0);
        conv_issue_tma(&tmx, &tmw, sb, 2, b, i0);
        for (int s = 0; s < 18; s++) {
            int st = s % NSTAGE;
            int ph = (s / NSTAGE) & 1;
            MBARRIER_WAIT_PARITY(sb + SM_BAR_FULL + st * 8, ph);
            uint32_t sbase = sb + SM_STAGE + st * STAGE_BYTES;
            uint64_t bd = MAKE_SMEM_DESC(sbase);
            uint64_t a0 = MAKE_SMEM_DESC(sbase + OFF_A0);
            uint64_t a1 = MAKE_SMEM_DESC(sbase + OFF_A1);
#pragma unroll
            for (int kk = 0; kk < 4; kk++) {
                bool acc = !(s == 0 && kk == 0);
                mma_f16_ss(tmem,       a0 + 2 * kk, bd + 2 * kk, CONV_IDESC, acc);
                mma_f16_ss(tmem + 256, a1 + 2 * kk, bd + 2 * kk, CONV_IDESC, acc);
            }
            if (s + NSTAGE < 18) {
                TCGEN05_COMMIT(sb + SM_BAR_EMPTY + st * 8);
                MBARRIER_WAIT_PARITY(sb + SM_BAR_EMPTY + st * 8, ph);
                conv_issue_tma(&tmx, &tmw, sb, s + NSTAGE, b, i0);
            } else if (s == 17) {
                TCGEN05_COMMIT(sb + SM_BAR_DONE);
            }
        }
    }

    MBARRIER_WAIT_PARITY(sb + SM_BAR_DONE, 0);
    TCGEN05_FENCE_AFTER();

    // 8 warps: wid>>2 = row select, wid&3 = lane subpartition (pixel group)
    int r = wid >> 2;
    int i = i0 + r;
    int j = (wid & 3) * 32 + lane;
    const float* cn = reinterpret_cast<const float*>(smem + SM_CN);
    uint32_t dbase = tmem + r * 256;
    for (int c0 = 0; c0 < NN; c0 += 32) {
        uint32_t reg[32];
        TCGEN05_LD_32X32B_X32(reg, dbase + c0);
        TCGEN05_WAIT_LD();
        if (j < WW) {
            float* po = out + (((size_t)(b * NN + c0)) * HH + i) * WW + j;
#pragma unroll
            for (int c = 0; c < 32; c++)
                po[(size_t)c * (HH * WW)] = __uint_as_float(reg[c]) - cn[c0 + c];
        }
    }
    TCGEN05_FENCE_BEFORE();
    __syncthreads();
    if (wid == 0) TCGEN05_DEALLOC(tmem, 512);

#else
    // -------- compile-only fallback for plain sm_103 (never selected at load
    // time on GB300 since an sm_103a cubin exists in the same fatbin) --------
    __syncthreads();
    const float* cn_g = g_cn;
    for (int t = tid; t < 2 * NN * WW; t += 256) {
        int j = t % WW;
        int n = (t / WW) % NN;
        int r = t / (WW * NN);
        int i = i0 + r;
        float acc = 0.f;
        for (int p = 0; p < 3; p++)
            for (int q = 0; q < 3; q++) {
                const __nv_bfloat16* a =
                    g_xp + (((size_t)b * HP + (i + p)) * WP + (j + q)) * C2;
                const __nv_bfloat16* wv = g_wk + ((size_t)(p * 3 + q) * NN + n) * C2;
                for (int c = 0; c < C2; c++)
                    acc += __bfloat162float(a[c]) * __bfloat162float(wv[c]);
            }
        out[(((size_t)(b * NN + n)) * HH + i) * WW + j] = acc - cn_g[n];
    }
#endif
}

// ---------------- host launcher ----------------
typedef CUresult (*PFN_encodeTiled)(
    CUtensorMap*, CUtensorMapDataType, cuuint32_t, void*,
    const cuuint64_t*, const cuuint64_t*, const cuuint32_t*, const cuuint32_t*,
    CUtensorMapInterleave, CUtensorMapSwizzle, CUtensorMapL2promotion,
    CUtensorMapFloatOOBfill);

extern "C" void kernel_launch(void* const* d_in, const int* in_sizes, int n_in,
                              void* d_out, int out_size) {
    const float* x  = (const float*)d_in[0];
    const float* sw = (const float*)d_in[1];
    const float* tm = (const float*)d_in[2];
    float* out = (float*)d_out;

    static PFN_encodeTiled enc = nullptr;
    if (!enc) {
        void* fp = nullptr;
        cudaDriverEntryPointQueryResult qr;
        cudaGetDriverEntryPoint("cuTensorMapEncodeTiled", &fp, cudaEnableDefault, &qr);
        enc = (PFN_encodeTiled)fp;
    }
    if (!enc) return;

    void* xp_ptr = nullptr;
    void* wk_ptr = nullptr;
    cudaGetSymbolAddress(&xp_ptr, g_xp);
    cudaGetSymbolAddress(&wk_ptr, g_wk);

    CUtensorMap tmx, tmw;
    {
        cuuint64_t dims[3]    = {C2, WP, (cuuint64_t)BB * HP};
        cuuint64_t strides[2] = {(cuuint64_t)C2 * 2, (cuuint64_t)WP * C2 * 2};
        cuuint32_t box[3]     = {64, 128, 1};
        cuuint32_t es[3]      = {1, 1, 1};
        enc(&tmx, CU_TENSOR_MAP_DATA_TYPE_BFLOAT16, 3, xp_ptr, dims, strides, box, es,
            CU_TENSOR_MAP_INTERLEAVE_NONE, CU_TENSOR_MAP_SWIZZLE_128B,
            CU_TENSOR_MAP_L2_PROMOTION_L2_128B, CU_TENSOR_MAP_FLOAT_OOB_FILL_NONE);
    }
    {
        cuuint64_t dims[3]    = {C2, NN, 9};
        cuuint64_t strides[2] = {(cuuint64_t)C2 * 2, (cuuint64_t)NN * C2 * 2};
        cuuint32_t box[3]     = {64, 256, 1};
        cuuint32_t es[3]      = {1, 1, 1};
        enc(&tmw, CU_TENSOR_MAP_DATA_TYPE_BFLOAT16, 3, wk_ptr, dims, strides, box, es,
            CU_TENSOR_MAP_INTERLEAVE_NONE, CU_TENSOR_MAP_SWIZZLE_128B,
            CU_TENSOR_MAP_L2_PROMOTION_L2_128B, CU_TENSOR_MAP_FLOAT_OOB_FILL_NONE);
    }

    cudaFuncSetAttribute(sim_conv, cudaFuncAttributeMaxDynamicSharedMemorySize, CONV_SMEM);

    sim_fill_xp<<<dim3(5, HP, BB), 256>>>(x);
    sim_prep_w<<<NN, 64>>>(sw, tm);
    sim_conv<<<BB * (HH / 2), 256, CONV_SMEM>>>(tmx, tmw, out);
}

// round 4
// speedup vs baseline: 1.2501x; 1.1730x over previous
#include <cuda_runtime.h>
#include <cuda.h>
#include <cuda_bf16.h>
#include <cstdint>

// ---------------- arch feature detection ----------------
#if defined(__CUDA_ARCH__)
#  if defined(__CUDA_ARCH_FEAT_SM103_ALL) || defined(__CUDA_ARCH_FEAT_SM100_ALL) || \
      (defined(__CUDA_ARCH_SPECIFIC__) && (__CUDA_ARCH_SPECIFIC__ >= 1000)) || \
      (defined(__CUDA_ARCH_FAMILY_SPECIFIC__) && (__CUDA_ARCH_FAMILY_SPECIFIC__ >= 1000))
#    define HAS_TCGEN05 1
#  else
#    define HAS_TCGEN05 0
#  endif
#else
#  define HAS_TCGEN05 0
#endif

// ---------------- problem dims ----------------
#define BB 16
#define CC 64
#define HH 112
#define WW 112
#define NN 256
#define HP 114
#define WP 144
#define C2 128

// ---------------- device scratch ----------------
static __device__ __align__(1024) __nv_bfloat16 g_xp[(size_t)BB * HP * WP * C2]; // ~67 MB
static __device__ __align__(1024) __nv_bfloat16 g_wk[9 * NN * C2];               // ~590 KB
static __device__ float g_cn[NN];

// ---------------- PTX helpers ----------------
__device__ __forceinline__ uint32_t smem_to_u32(const void* smem_ptr) {
    uint32_t addr;
    asm("{ .reg .u64 tmp; cvta.to.shared.u64 tmp, %1; cvt.u32.u64 %0, tmp; }"
        : "=r"(addr) : "l"(smem_ptr));
    return addr;
}

#define MBARRIER_INIT(mbar_smem_addr, count) \
    asm volatile("mbarrier.init.shared.b64 [%0], %1;" \
        :: "r"((uint32_t)(mbar_smem_addr)), "r"((uint32_t)(count)) : "memory")
#define MBARRIER_EXPECT_TX(mbar_smem_addr, tx_bytes) \
    asm volatile("mbarrier.arrive.expect_tx.shared.b64 _, [%0], %1;" \
        :: "r"((uint32_t)(mbar_smem_addr)), "r"((uint32_t)(tx_bytes)) : "memory")

#define MBARRIER_WAIT_PARITY(mbar_smem_addr, phase_parity) do { \
    uint32_t _mbar = (uint32_t)(mbar_smem_addr); \
    uint32_t _parity = (uint32_t)(phase_parity); \
    uint32_t _done; \
    asm volatile( \
        "{\n\t.reg .pred p;\n\t" \
        "mbarrier.try_wait.parity.acquire.cta.shared::cta.b64 p, [%1], %2;\n\t" \
        "selp.b32 %0, 1, 0, p;\n\t}" \
        : "=r"(_done) : "r"(_mbar), "r"(_parity) : "memory"); \
    if (!_done) { \
        asm volatile( \
            "{\n\t.reg .pred P1;\n\t" \
            "WAIT_LOOP_%=:\n\t" \
            "mbarrier.try_wait.parity.acquire.cta.shared::cta.b64 P1, [%0], %1, 0x989680;\n\t" \
            "@P1 bra.uni WAIT_DONE_%=;\n\t" \
            "bra.uni WAIT_LOOP_%=;\n\t" \
            "WAIT_DONE_%=:\n\t}" \
            :: "r"(_mbar), "r"(_parity) : "memory"); \
    } \
} while (0)

#define TMA_LOAD_3D(smem_addr, tensor_map, coord_x, coord_y, coord_z, mbar_smem_addr) \
    asm volatile( \
        "cp.async.bulk.tensor.3d.shared::cta.global.tile.mbarrier::complete_tx::bytes " \
        "[%0], [%1, {%2, %3, %4}], [%5];" \
        :: "r"((uint32_t)(smem_addr)), "l"(tensor_map), \
           "r"((int32_t)(coord_x)), "r"((int32_t)(coord_y)), "r"((int32_t)(coord_z)), \
           "r"((uint32_t)(mbar_smem_addr)) : "memory")

#if HAS_TCGEN05
#define TCGEN05_ALLOC(smem_result_addr, nCols) \
    asm volatile("tcgen05.alloc.cta_group::1.sync.aligned.shared::cta.b32 [%0], %1;" \
        :: "r"((uint32_t)(smem_result_addr)), "r"((uint32_t)(nCols)) : "memory")
#define TCGEN05_DEALLOC(tmem_addr, nCols) \
    asm volatile("tcgen05.dealloc.cta_group::1.sync.aligned.b32 %0, %1;" \
        :: "r"(tmem_addr), "r"((uint32_t)(nCols)))
#define TCGEN05_RELINQUISH_ALLOC_PERMIT() \
    asm volatile("tcgen05.relinquish_alloc_permit.cta_group::1.sync.aligned;")
#define TCGEN05_COMMIT(mbar_smem_addr) \
    asm volatile("tcgen05.commit.cta_group::1.mbarrier::arrive::one.shared::cluster.b64 [%0];" \
        :: "r"((uint32_t)(mbar_smem_addr)) : "memory")
#define TCGEN05_FENCE_AFTER() \
    asm volatile("tcgen05.fence::after_thread_sync;" ::: "memory")
#define TCGEN05_FENCE_BEFORE() \
    asm volatile("tcgen05.fence::before_thread_sync;" ::: "memory")
#define TCGEN05_WAIT_LD() \
    asm volatile("tcgen05.wait::ld.sync.aligned;" ::: "memory")

#define TCGEN05_LD_32X32B_X32(r, tmem_addr) \
    asm volatile( \
        "tcgen05.ld.sync.aligned.32x32b.x32.b32 " \
        "{%0, %1, %2, %3, %4, %5, %6, %7, " \
        " %8, %9, %10, %11, %12, %13, %14, %15, " \
        " %16, %17, %18, %19, %20, %21, %22, %23, " \
        " %24, %25, %26, %27, %28, %29, %30, %31}, [%32];" \
        : "=r"((r)[0]),  "=r"((r)[1]),  "=r"((r)[2]),  "=r"((r)[3]), \
          "=r"((r)[4]),  "=r"((r)[5]),  "=r"((r)[6]),  "=r"((r)[7]), \
          "=r"((r)[8]),  "=r"((r)[9]),  "=r"((r)[10]), "=r"((r)[11]), \
          "=r"((r)[12]), "=r"((r)[13]), "=r"((r)[14]), "=r"((r)[15]), \
          "=r"((r)[16]), "=r"((r)[17]), "=r"((r)[18]), "=r"((r)[19]), \
          "=r"((r)[20]), "=r"((r)[21]), "=r"((r)[22]), "=r"((r)[23]), \
          "=r"((r)[24]), "=r"((r)[25]), "=r"((r)[26]), "=r"((r)[27]), \
          "=r"((r)[28]), "=r"((r)[29]), "=r"((r)[30]), "=r"((r)[31]) \
        : "r"(tmem_addr))

static constexpr uint64_t SMEM_DESC_BASE_SW128 =
    (uint64_t(2) << 61) | (uint64_t(1) << 46) | (uint64_t(64) << 32) | (uint64_t(1) << 16);
#define MAKE_SMEM_DESC(base_addr) \
    (SMEM_DESC_BASE_SW128 | ((uint64_t)((base_addr) >> 4) & 0x3FFF))

__device__ __forceinline__ void mma_f16_ss(uint32_t d_tmem, uint64_t a_desc, uint64_t b_desc,
                                           uint32_t idesc, bool acc) {
    uint32_t en = acc ? 1u : 0u;
    asm volatile(
        "{\n\t.reg .pred p;\n\t"
        "setp.ne.u32 p, %5, 0;\n\t"
        "tcgen05.mma.cta_group::1.kind::f16 [%0], %1, %2, %3, {%4, %4, %4, %4}, p;\n\t}"
        :: "r"(d_tmem), "l"(a_desc), "l"(b_desc), "r"(idesc), "r"(0u), "r"(en)
        : "memory");
}
#endif  // HAS_TCGEN05

// ---------------- preprocessing kernels ----------------
__global__ void sim_fill_xp(const float* __restrict__ x) {
    __shared__ float tile[64][33];
    int pw0 = blockIdx.x * 32;
    int py = blockIdx.y;
    int b = blockIdx.z;
    int lane = threadIdx.x & 31, warp = threadIdx.x >> 5;
    int h = py - 1;
    bool rowvalid = (py >= 1 && py <= WW);
    int w = pw0 + lane - 1;
#pragma unroll
    for (int k = 0; k < 8; k++) {
        int c = warp * 8 + k;
        float v = 0.f;
        if (rowvalid && w >= 0 && w < WW)
            v = x[(((size_t)b * CC + c) * HH + h) * WW + w];
        tile[c][lane] = v;
    }
    __syncthreads();
    int p = threadIdx.x >> 3, cg = threadIdx.x & 7;
    int pw = pw0 + p;
    if (pw < WP) {
        __nv_bfloat16* dst = g_xp + (((size_t)b * HP + py) * WP + pw) * C2;
        __nv_bfloat162 sq[4], xv[4];
#pragma unroll
        for (int t = 0; t < 4; t++) {
            float v0 = tile[cg * 8 + 2 * t][p];
            float v1 = tile[cg * 8 + 2 * t + 1][p];
            sq[t] = __floats2bfloat162_rn(v0 * v0, v1 * v1);
            xv[t] = __floats2bfloat162_rn(v0, v1);
        }
        *reinterpret_cast<uint4*>(dst + cg * 8) = *reinterpret_cast<const uint4*>(sq);
        *reinterpret_cast<uint4*>(dst + 64 + cg * 8) = *reinterpret_cast<const uint4*>(xv);
    }
}

__global__ void sim_prep_w(const float* __restrict__ sw, const float* __restrict__ tm) {
    int n = blockIdx.x, c = threadIdx.x;
    float csum = 0.f;
#pragma unroll
    for (int p = 0; p < 3; p++)
#pragma unroll
        for (int q = 0; q < 3; q++) {
            size_t idx = (((size_t)n * CC + c) * 3 + p) * 3 + q;
            float w = fabsf(sw[idx]);
            float t = tm[idx];
            csum += w * t * t;
            size_t o = ((size_t)(p * 3 + q) * NN + n) * C2;
            g_wk[o + c] = __float2bfloat16(-w);
            g_wk[o + 64 + c] = __float2bfloat16(2.f * w * t);
        }
    __shared__ float red[64];
    red[c] = csum;
    __syncthreads();
    for (int s = 32; s > 0; s >>= 1) {
        if (c < s) red[c] += red[c + s];
        __syncthreads();
    }
    if (c == 0) g_cn[n] = red[0];
}

// ---------------- main conv kernel ----------------
// R=2 output rows per CTA; 18 sub-stages of 64KB ([B half 32K][A0 16K][A1 16K]);
// 3-deep pipeline; warp-specialized: warp0=TMA producer, warp1=MMA consumer.
#define SM_TMEM      0
#define SM_BAR_FULL  16    // 16,24,32
#define SM_BAR_EMPTY 48    // 48,56,64
#define SM_BAR_DONE  80
#define SM_CN        1024
#define SM_STAGE     2048
#define STAGE_BYTES  65536
#define OFF_A0       32768
#define OFF_A1       49152
#define NSTAGE       3
#define NSUB         18
#define CONV_SMEM    (SM_STAGE + NSTAGE * STAGE_BYTES)   // 198656

#if HAS_TCGEN05
static constexpr uint32_t CONV_IDESC =
    (1u << 4) | (1u << 7) | (1u << 10) | ((NN / 8) << 17) | ((128 / 16) << 24);

__device__ __forceinline__ void conv_issue_tma(
    const CUtensorMap* tmx, const CUtensorMap* tmw,
    uint32_t sb, int s, int b, int i0)
{
    int step = s >> 1, kh = s & 1;
    int p = step / 3, q = step % 3;
    int st = s % NSTAGE;
    uint32_t sbase = sb + SM_STAGE + st * STAGE_BYTES;
    uint32_t bar = sb + SM_BAR_FULL + st * 8;
    MBARRIER_EXPECT_TX(bar, STAGE_BYTES);
    int z = b * HP + i0 + p;
    TMA_LOAD_3D(sbase,           tmw, 64 * kh, 0, step, bar);   // B half [256n x 64c]
    TMA_LOAD_3D(sbase + OFF_A0,  tmx, 64 * kh, q, z,     bar);  // A row0 half
    TMA_LOAD_3D(sbase + OFF_A1,  tmx, 64 * kh, q, z + 1, bar);  // A row1 half
}
#endif

__global__ void __launch_bounds__(256, 1) sim_conv(
    const __grid_constant__ CUtensorMap tmx,
    const __grid_constant__ CUtensorMap tmw,
    float* __restrict__ out)
{
    extern __shared__ char smem[];
    uint32_t sb = smem_to_u32(smem);
    int tid = threadIdx.x, wid = tid >> 5, lane = tid & 31;
    int bx = blockIdx.x;
    int b = bx / (HH / 2), i0 = (bx % (HH / 2)) * 2;

    for (int k = tid; k < NN; k += 256)
        reinterpret_cast<float*>(smem + SM_CN)[k] = g_cn[k];
    if (tid == 0) {
#pragma unroll
        for (int s = 0; s < NSTAGE; s++) {
            MBARRIER_INIT(sb + SM_BAR_FULL + s * 8, 1);
            MBARRIER_INIT(sb + SM_BAR_EMPTY + s * 8, 1);
        }
        MBARRIER_INIT(sb + SM_BAR_DONE, 1);
    }

#if HAS_TCGEN05
    if (wid == 0) {
        TCGEN05_ALLOC(sb + SM_TMEM, 512);
        TCGEN05_RELINQUISH_ALLOC_PERMIT();
    }
    __syncthreads();

    uint32_t tmem;
    asm volatile("ld.shared.b32 %0, [%1];" : "=r"(tmem) : "r"(sb + SM_TMEM));

    if (tid == 0) {
        // -------- TMA producer --------
        for (int s = 0; s < NSUB; s++) {
            if (s >= NSTAGE) {
                int st = s % NSTAGE;
                int ph = ((s - NSTAGE) / NSTAGE) & 1;
                MBARRIER_WAIT_PARITY(sb + SM_BAR_EMPTY + st * 8, ph);
            }
            conv_issue_tma(&tmx, &tmw, sb, s, b, i0);
        }
    } else if (tid == 32) {
        // -------- MMA consumer --------
        for (int s = 0; s < NSUB; s++) {
            int st = s % NSTAGE;
            int ph = (s / NSTAGE) & 1;
            MBARRIER_WAIT_PARITY(sb + SM_BAR_FULL + st * 8, ph);
            uint32_t sbase = sb + SM_STAGE + st * STAGE_BYTES;
            uint64_t bd = MAKE_SMEM_DESC(sbase);
            uint64_t a0 = MAKE_SMEM_DESC(sbase + OFF_A0);
            uint64_t a1 = MAKE_SMEM_DESC(sbase + OFF_A1);
#pragma unroll
            for (int kk = 0; kk < 4; kk++) {
                bool acc = !(s == 0 && kk == 0);
                mma_f16_ss(tmem,       a0 + 2 * kk, bd + 2 * kk, CONV_IDESC, acc);
                mma_f16_ss(tmem + 256, a1 + 2 * kk, bd + 2 * kk, CONV_IDESC, acc);
            }
            TCGEN05_COMMIT(sb + SM_BAR_EMPTY + st * 8);
        }
        TCGEN05_COMMIT(sb + SM_BAR_DONE);
    }

    MBARRIER_WAIT_PARITY(sb + SM_BAR_DONE, 0);
    TCGEN05_FENCE_AFTER();

    // 8 warps: wid>>2 = row select, wid&3 = pixel group
    int r = wid >> 2;
    int i = i0 + r;
    int j = (wid & 3) * 32 + lane;
    const float* cn = reinterpret_cast<const float*>(smem + SM_CN);
    uint32_t dbase = tmem + r * 256;
    for (int c0 = 0; c0 < NN; c0 += 32) {
        uint32_t reg[32];
        TCGEN05_LD_32X32B_X32(reg, dbase + c0);
        TCGEN05_WAIT_LD();
        if (j < WW) {
            float* po = out + (((size_t)(b * NN + c0)) * HH + i) * WW + j;
#pragma unroll
            for (int c = 0; c < 32; c++)
                po[(size_t)c * (HH * WW)] = __uint_as_float(reg[c]) - cn[c0 + c];
        }
    }
    TCGEN05_FENCE_BEFORE();
    __syncthreads();
    if (wid == 0) TCGEN05_DEALLOC(tmem, 512);

#else
    // -------- compile-only fallback for plain sm_103 --------
    __syncthreads();
    const float* cn_g = g_cn;
    for (int t = tid; t < 2 * NN * WW; t += 256) {
        int j = t % WW;
        int n = (t / WW) % NN;
        int r = t / (WW * NN);
        int i = i0 + r;
        float acc = 0.f;
        for (int p = 0; p < 3; p++)
            for (int q = 0; q < 3; q++) {
                const __nv_bfloat16* a =
                    g_xp + (((size_t)b * HP + (i + p)) * WP + (j + q)) * C2;
                const __nv_bfloat16* wv = g_wk + ((size_t)(p * 3 + q) * NN + n) * C2;
                for (int c = 0; c < C2; c++)
                    acc += __bfloat162float(a[c]) * __bfloat162float(wv[c]);
            }
        out[(((size_t)(b * NN + n)) * HH + i) * WW + j] = acc - cn_g[n];
    }
#endif
}

// ---------------- host launcher ----------------
typedef CUresult (*PFN_encodeTiled)(
    CUtensorMap*, CUtensorMapDataType, cuuint32_t, void*,
    const cuuint64_t*, const cuuint64_t*, const cuuint32_t*, const cuuint32_t*,
    CUtensorMapInterleave, CUtensorMapSwizzle, CUtensorMapL2promotion,
    CUtensorMapFloatOOBfill);

extern "C" void kernel_launch(void* const* d_in, const int* in_sizes, int n_in,
                              void* d_out, int out_size) {
    const float* x  = (const float*)d_in[0];
    const float* sw = (const float*)d_in[1];
    const float* tm = (const float*)d_in[2];
    float* out = (float*)d_out;

    static PFN_encodeTiled enc = nullptr;
    if (!enc) {
        void* fp = nullptr;
        cudaDriverEntryPointQueryResult qr;
        cudaGetDriverEntryPoint("cuTensorMapEncodeTiled", &fp, cudaEnableDefault, &qr);
        enc = (PFN_encodeTiled)fp;
    }
    if (!enc) return;

    void* xp_ptr = nullptr;
    void* wk_ptr = nullptr;
    cudaGetSymbolAddress(&xp_ptr, g_xp);
    cudaGetSymbolAddress(&wk_ptr, g_wk);

    CUtensorMap tmx, tmw;
    {
        cuuint64_t dims[3]    = {C2, WP, (cuuint64_t)BB * HP};
        cuuint64_t strides[2] = {(cuuint64_t)C2 * 2, (cuuint64_t)WP * C2 * 2};
        cuuint32_t box[3]     = {64, 128, 1};
        cuuint32_t es[3]      = {1, 1, 1};
        enc(&tmx, CU_TENSOR_MAP_DATA_TYPE_BFLOAT16, 3, xp_ptr, dims, strides, box, es,
            CU_TENSOR_MAP_INTERLEAVE_NONE, CU_TENSOR_MAP_SWIZZLE_128B,
            CU_TENSOR_MAP_L2_PROMOTION_L2_128B, CU_TENSOR_MAP_FLOAT_OOB_FILL_NONE);
    }
    {
        cuuint64_t dims[3]    = {C2, NN, 9};
        cuuint64_t strides[2] = {(cuuint64_t)C2 * 2, (cuuint64_t)NN * C2 * 2};
        cuuint32_t box[3]     = {64, 256, 1};
        cuuint32_t es[3]      = {1, 1, 1};
        enc(&tmw, CU_TENSOR_MAP_DATA_TYPE_BFLOAT16, 3, wk_ptr, dims, strides, box, es,
            CU_TENSOR_MAP_INTERLEAVE_NONE, CU_TENSOR_MAP_SWIZZLE_128B,
            CU_TENSOR_MAP_L2_PROMOTION_L2_128B, CU_TENSOR_MAP_FLOAT_OOB_FILL_NONE);
    }

    cudaFuncSetAttribute(sim_conv, cudaFuncAttributeMaxDynamicSharedMemorySize, CONV_SMEM);

    sim_fill_xp<<<dim3(5, HP, BB), 256>>>(x);
    sim_prep_w<<<NN, 64>>>(sw, tm);
    sim_conv<<<BB * (HH / 2), 256, CONV_SMEM>>>(tmx, tmw, out);
}